// round 1
// baseline (speedup 1.0000x reference)
#include <cuda_runtime.h>
#include <math.h>
#include <stdint.h>

// ---------------- problem constants ----------------
#define NTOK 8192
#define DDIM 1024
#define HDIM 4096
#define ODIM 1024
#define NEXP 8
#define TOPK 3
#define NSLOT (NTOK * TOPK)   // 24576 token-expert pairs

// ---------------- static device scratch (no allocations allowed) ----------------
__device__ int   g_count[NEXP];
__device__ int   g_offset[NEXP];
__device__ int   g_cursor[NEXP];
__device__ int   g_topk_e[NTOK * TOPK];
__device__ float g_topk_w[NTOK * TOPK];
__device__ int   g_slot_token[NSLOT];
__device__ float g_slot_weight[NSLOT];
// h activations: 24576 x 4096 fp32 = 402.7 MB
__device__ float g_h[(size_t)NSLOT * HDIM];

// ---------------- helpers ----------------
__device__ __forceinline__ unsigned tf32_rna(float f) {
    unsigned u;
    asm("cvt.rna.tf32.f32 %0, %1;" : "=r"(u) : "f"(f));
    return u;
}

__device__ __forceinline__ void mma_tf32(float* d, const unsigned* a, const unsigned* b) {
    asm volatile(
        "mma.sync.aligned.m16n8k8.row.col.f32.tf32.tf32.f32 "
        "{%0,%1,%2,%3}, {%4,%5,%6,%7}, {%8,%9}, {%0,%1,%2,%3};\n"
        : "+f"(d[0]), "+f"(d[1]), "+f"(d[2]), "+f"(d[3])
        : "r"(a[0]), "r"(a[1]), "r"(a[2]), "r"(a[3]),
          "r"(b[0]), "r"(b[1]));
}

// ---------------- init: zero per-expert counters (graph replays!) ----------------
__global__ void init_counts_kernel() {
    if (threadIdx.x < NEXP) g_count[threadIdx.x] = 0;
}

// ---------------- gate: one warp per token ----------------
__global__ void gate_kernel(const float* __restrict__ x,
                            const float* __restrict__ gw,
                            const float* __restrict__ gb) {
    int tok  = (blockIdx.x * blockDim.x + threadIdx.x) >> 5;
    int lane = threadIdx.x & 31;
    if (tok >= NTOK) return;

    const float* xr = x + (size_t)tok * DDIM;
    float part[NEXP];
#pragma unroll
    for (int e = 0; e < NEXP; e++) part[e] = 0.0f;

#pragma unroll 4
    for (int j = 0; j < DDIM / 32; j++) {
        int d = j * 32 + lane;
        float xv = xr[d];
        const float4* gp = reinterpret_cast<const float4*>(gw + (size_t)d * NEXP);
        float4 a = gp[0];
        float4 b = gp[1];
        part[0] += xv * a.x; part[1] += xv * a.y;
        part[2] += xv * a.z; part[3] += xv * a.w;
        part[4] += xv * b.x; part[5] += xv * b.y;
        part[6] += xv * b.z; part[7] += xv * b.w;
    }
#pragma unroll
    for (int off = 16; off > 0; off >>= 1) {
#pragma unroll
        for (int e = 0; e < NEXP; e++)
            part[e] += __shfl_xor_sync(0xffffffffu, part[e], off);
    }

    if (lane == 0) {
        float s[NEXP];
#pragma unroll
        for (int e = 0; e < NEXP; e++) s[e] = part[e] + gb[e];

        // top-3 (strict >, ties keep earliest index like lax.top_k)
        int id[TOPK];
        bool used[NEXP];
#pragma unroll
        for (int e = 0; e < NEXP; e++) used[e] = false;
#pragma unroll
        for (int k = 0; k < TOPK; k++) {
            float best = -1e30f;
            int bi = 0;
#pragma unroll
            for (int e = 0; e < NEXP; e++) {
                if (!used[e] && s[e] > best) { best = s[e]; bi = e; }
            }
            used[bi] = true;
            id[k] = bi;
        }

        float mx = s[0];
#pragma unroll
        for (int e = 1; e < NEXP; e++) mx = fmaxf(mx, s[e]);
        float p[NEXP], tot = 0.0f;
#pragma unroll
        for (int e = 0; e < NEXP; e++) { p[e] = expf(s[e] - mx); tot += p[e]; }
        float inv = 1.0f / tot;
        float msum = (p[id[0]] + p[id[1]] + p[id[2]]) * inv;
        float den = msum + 1e-8f;

#pragma unroll
        for (int k = 0; k < TOPK; k++) {
            int e = id[k];
            float w = (p[e] * inv) / den;
            g_topk_e[tok * TOPK + k] = e;
            g_topk_w[tok * TOPK + k] = w;
            atomicAdd(&g_count[e], 1);
        }
    }
}

// ---------------- exclusive scan over 8 experts + zero cursors ----------------
__global__ void offsets_kernel() {
    if (threadIdx.x == 0 && blockIdx.x == 0) {
        int off = 0;
#pragma unroll
        for (int e = 0; e < NEXP; e++) {
            g_offset[e] = off;
            off += g_count[e];
            g_cursor[e] = 0;
        }
    }
}

// ---------------- scatter tokens into compact per-expert lists ----------------
__global__ void scatter_kernel() {
    int t = blockIdx.x * blockDim.x + threadIdx.x;
    if (t >= NTOK) return;
#pragma unroll
    for (int k = 0; k < TOPK; k++) {
        int e = g_topk_e[t * TOPK + k];
        int pos = atomicAdd(&g_cursor[e], 1);
        int i = g_offset[e] + pos;
        g_slot_token[i] = t;
        g_slot_weight[i] = g_topk_w[t * TOPK + k];
    }
}

// ---------------- grouped GEMM (tf32 mma.sync), 64x64x32 tiles ----------------
// FIRST=true : h = relu(gather(x) @ w1[e] + b1[e]) -> g_h   (KDIM=1024, NDIM=4096)
// FIRST=false: out += weight * (g_h @ w2[e] + b2[e])        (KDIM=4096, NDIM=1024)
template <int KDIM, int NDIM, bool FIRST>
__global__ __launch_bounds__(128) void moe_gemm_kernel(
    const float* __restrict__ A,     // x when FIRST, unused otherwise (g_h used)
    const float* __restrict__ B,     // w1 or w2, [E, KDIM, NDIM]
    const float* __restrict__ bias,  // b1 or b2, [E, NDIM]
    float* __restrict__ out)         // final output when !FIRST
{
    const int e = blockIdx.z;
    const int cnt = g_count[e];
    const int m0 = blockIdx.y * 64;
    if (m0 >= cnt) return;
    const int base = g_offset[e];
    const int n0 = blockIdx.x * 64;

    // strides chosen for conflict-free mma fragment reads + 16B-aligned stores
    __shared__ __align__(16) unsigned As[64][36];
    __shared__ __align__(16) unsigned Bs[32][68];
    __shared__ int stok[64];

    const int tid = threadIdx.x;
    if (FIRST) {
        if (tid < 64) {
            int r = m0 + tid;
            stok[tid] = (r < cnt) ? g_slot_token[base + r] : -1;
        }
    }
    __syncthreads();

    const float* Ap = FIRST ? A : (const float*)g_h;
    const float* Bp = B + (size_t)e * KDIM * NDIM;

    float acc[2][4][4];
#pragma unroll
    for (int mi = 0; mi < 2; mi++)
#pragma unroll
        for (int ni = 0; ni < 4; ni++)
#pragma unroll
            for (int r = 0; r < 4; r++) acc[mi][ni][r] = 0.0f;

    const int lane = tid & 31;
    const int w = tid >> 5;
    const int gq = lane >> 2;   // groupID 0..7
    const int tg = lane & 3;    // threadID in group 0..3
    const int wm = w >> 1, wn = w & 1;

    for (int k0 = 0; k0 < KDIM; k0 += 32) {
        // --- load A tile: 64 rows x 32 cols ---
#pragma unroll
        for (int j = 0; j < 4; j++) {
            int u = tid + j * 128;
            int row = u >> 3;
            int c4 = (u & 7) * 4;
            float4 v = make_float4(0.f, 0.f, 0.f, 0.f);
            if (FIRST) {
                int tokr = stok[row];
                if (tokr >= 0)
                    v = *reinterpret_cast<const float4*>(Ap + (size_t)tokr * KDIM + k0 + c4);
            } else {
                if (m0 + row < cnt)
                    v = *reinterpret_cast<const float4*>(
                        Ap + (size_t)(base + m0 + row) * KDIM + k0 + c4);
            }
            uint4 t4;
            t4.x = tf32_rna(v.x); t4.y = tf32_rna(v.y);
            t4.z = tf32_rna(v.z); t4.w = tf32_rna(v.w);
            *reinterpret_cast<uint4*>(&As[row][c4]) = t4;
        }
        // --- load B tile: 32 rows (k) x 64 cols (n) ---
#pragma unroll
        for (int j = 0; j < 4; j++) {
            int u = tid + j * 128;
            int row = u >> 4;
            int c4 = (u & 15) * 4;
            float4 v = *reinterpret_cast<const float4*>(
                Bp + (size_t)(k0 + row) * NDIM + n0 + c4);
            uint4 t4;
            t4.x = tf32_rna(v.x); t4.y = tf32_rna(v.y);
            t4.z = tf32_rna(v.z); t4.w = tf32_rna(v.w);
            *reinterpret_cast<uint4*>(&Bs[row][c4]) = t4;
        }
        __syncthreads();

#pragma unroll
        for (int kk = 0; kk < 32; kk += 8) {
            unsigned afr[2][4], bfr[4][2];
#pragma unroll
            for (int mi = 0; mi < 2; mi++) {
                int r0 = wm * 32 + mi * 16 + gq;
                afr[mi][0] = As[r0][kk + tg];
                afr[mi][1] = As[r0 + 8][kk + tg];
                afr[mi][2] = As[r0][kk + tg + 4];
                afr[mi][3] = As[r0 + 8][kk + tg + 4];
            }
#pragma unroll
            for (int ni = 0; ni < 4; ni++) {
                int c0 = wn * 32 + ni * 8 + gq;
                bfr[ni][0] = Bs[kk + tg][c0];
                bfr[ni][1] = Bs[kk + tg + 4][c0];
            }
#pragma unroll
            for (int mi = 0; mi < 2; mi++)
#pragma unroll
                for (int ni = 0; ni < 4; ni++)
                    mma_tf32(acc[mi][ni], afr[mi], bfr[ni]);
        }
        __syncthreads();
    }

    // --- epilogue ---
#pragma unroll
    for (int mi = 0; mi < 2; mi++)
#pragma unroll
        for (int ni = 0; ni < 4; ni++)
#pragma unroll
            for (int r = 0; r < 4; r++) {
                int mrow = wm * 32 + mi * 16 + gq + ((r >= 2) ? 8 : 0);
                int ncol = wn * 32 + ni * 8 + 2 * tg + (r & 1);
                int slot = m0 + mrow;
                if (slot < cnt) {
                    int gn = n0 + ncol;
                    float v = acc[mi][ni][r] + bias[(size_t)e * NDIM + gn];
                    if (FIRST) {
                        g_h[(size_t)(base + slot) * NDIM + gn] = fmaxf(v, 0.0f);
                    } else {
                        float wgt = g_slot_weight[base + slot];
                        int tokw = g_slot_token[base + slot];
                        atomicAdd(out + (size_t)tokw * NDIM + gn, wgt * v);
                    }
                }
            }
}

// ---------------- launch ----------------
extern "C" void kernel_launch(void* const* d_in, const int* in_sizes, int n_in,
                              void* d_out, int out_size) {
    (void)in_sizes; (void)n_in;
    const float* x  = (const float*)d_in[0];
    const float* gw = (const float*)d_in[1];
    const float* gb = (const float*)d_in[2];
    const float* w1 = (const float*)d_in[3];
    const float* b1 = (const float*)d_in[4];
    const float* w2 = (const float*)d_in[5];
    const float* b2 = (const float*)d_in[6];
    float* out = (float*)d_out;

    cudaMemsetAsync(out, 0, (size_t)out_size * sizeof(float), 0);
    init_counts_kernel<<<1, 32>>>();
    gate_kernel<<<NTOK / 8, 256>>>(x, gw, gb);
    offsets_kernel<<<1, 32>>>();
    scatter_kernel<<<NTOK / 256, 256>>>();

    dim3 g1(HDIM / 64, NTOK / 64, NEXP);   // (64, 128, 8)
    moe_gemm_kernel<DDIM, HDIM, true><<<g1, 128>>>(x, w1, b1, nullptr);

    dim3 g2(ODIM / 64, NTOK / 64, NEXP);   // (16, 128, 8)
    moe_gemm_kernel<HDIM, ODIM, false><<<g2, 128>>>(nullptr, w2, b2, out);
}

// round 3
// speedup vs baseline: 1.2394x; 1.2394x over previous
#include <cuda_runtime.h>
#include <math.h>
#include <stdint.h>

// ---------------- problem constants ----------------
#define NTOK 8192
#define DDIM 1024
#define HDIM 4096
#define ODIM 1024
#define NEXP 8
#define TOPK 3
#define NSLOT (NTOK * TOPK)

// ---------------- static device scratch ----------------
__device__ int   g_count[NEXP];
__device__ int   g_offset[NEXP];
__device__ int   g_cursor[NEXP];
__device__ int   g_topk_e[NTOK * TOPK];
__device__ float g_topk_w[NTOK * TOPK];
__device__ int   g_slot_token[NSLOT];
__device__ float g_slot_weight[NSLOT];
__device__ float g_h[(size_t)NSLOT * HDIM];   // 402.7 MB

// ---------------- helpers ----------------
__device__ __forceinline__ unsigned tf32_rna(float f) {
    unsigned u;
    asm("cvt.rna.tf32.f32 %0, %1;" : "=r"(u) : "f"(f));
    return u;
}

__device__ __forceinline__ void mma_tf32(float* d, const unsigned* a, const unsigned* b) {
    asm volatile(
        "mma.sync.aligned.m16n8k8.row.col.f32.tf32.tf32.f32 "
        "{%0,%1,%2,%3}, {%4,%5,%6,%7}, {%8,%9}, {%0,%1,%2,%3};\n"
        : "+f"(d[0]), "+f"(d[1]), "+f"(d[2]), "+f"(d[3])
        : "r"(a[0]), "r"(a[1]), "r"(a[2]), "r"(a[3]),
          "r"(b[0]), "r"(b[1]));
}

// ---------------- init / gate / offsets / scatter (known-good from R1) ----------------
__global__ void init_counts_kernel() {
    if (threadIdx.x < NEXP) g_count[threadIdx.x] = 0;
}

__global__ void gate_kernel(const float* __restrict__ x,
                            const float* __restrict__ gw,
                            const float* __restrict__ gb) {
    int tok  = (blockIdx.x * blockDim.x + threadIdx.x) >> 5;
    int lane = threadIdx.x & 31;
    if (tok >= NTOK) return;

    const float* xr = x + (size_t)tok * DDIM;
    float part[NEXP];
#pragma unroll
    for (int e = 0; e < NEXP; e++) part[e] = 0.0f;

#pragma unroll 4
    for (int j = 0; j < DDIM / 32; j++) {
        int d = j * 32 + lane;
        float xv = xr[d];
        const float4* gp = reinterpret_cast<const float4*>(gw + (size_t)d * NEXP);
        float4 a = gp[0];
        float4 b = gp[1];
        part[0] += xv * a.x; part[1] += xv * a.y;
        part[2] += xv * a.z; part[3] += xv * a.w;
        part[4] += xv * b.x; part[5] += xv * b.y;
        part[6] += xv * b.z; part[7] += xv * b.w;
    }
#pragma unroll
    for (int off = 16; off > 0; off >>= 1)
#pragma unroll
        for (int e = 0; e < NEXP; e++)
            part[e] += __shfl_xor_sync(0xffffffffu, part[e], off);

    if (lane == 0) {
        float s[NEXP];
#pragma unroll
        for (int e = 0; e < NEXP; e++) s[e] = part[e] + gb[e];

        int id[TOPK];
        bool used[NEXP];
#pragma unroll
        for (int e = 0; e < NEXP; e++) used[e] = false;
#pragma unroll
        for (int k = 0; k < TOPK; k++) {
            float best = -1e30f;
            int bi = 0;
#pragma unroll
            for (int e = 0; e < NEXP; e++)
                if (!used[e] && s[e] > best) { best = s[e]; bi = e; }
            used[bi] = true;
            id[k] = bi;
        }

        float mx = s[0];
#pragma unroll
        for (int e = 1; e < NEXP; e++) mx = fmaxf(mx, s[e]);
        float p[NEXP], tot = 0.0f;
#pragma unroll
        for (int e = 0; e < NEXP; e++) { p[e] = expf(s[e] - mx); tot += p[e]; }
        float inv = 1.0f / tot;
        float msum = (p[id[0]] + p[id[1]] + p[id[2]]) * inv;
        float den = msum + 1e-8f;

#pragma unroll
        for (int k = 0; k < TOPK; k++) {
            int e = id[k];
            g_topk_e[tok * TOPK + k] = e;
            g_topk_w[tok * TOPK + k] = (p[e] * inv) / den;
            atomicAdd(&g_count[e], 1);
        }
    }
}

__global__ void offsets_kernel() {
    if (threadIdx.x == 0 && blockIdx.x == 0) {
        int off = 0;
#pragma unroll
        for (int e = 0; e < NEXP; e++) {
            g_offset[e] = off;
            off += g_count[e];
            g_cursor[e] = 0;
        }
    }
}

__global__ void scatter_kernel() {
    int t = blockIdx.x * blockDim.x + threadIdx.x;
    if (t >= NTOK) return;
#pragma unroll
    for (int k = 0; k < TOPK; k++) {
        int e = g_topk_e[t * TOPK + k];
        int pos = atomicAdd(&g_cursor[e], 1);
        int i = g_offset[e] + pos;
        g_slot_token[i] = t;
        g_slot_weight[i] = g_topk_w[t * TOPK + k];
    }
}

// ---------------- tf32 mma.sync grouped GEMM ----------------
// CTA tile 256x128, 8 warps of 64x64, K-tile 16, double-buffered smem,
// software-pipelined LDG -> cvt.rna -> STS. Conflict-free smem strides:
// A stride 20 words, B stride 136 words (see analysis).
#define BM 256
#define BN 128
#define BK 16
#define A_STRIDE 20
#define B_STRIDE 136
#define A_STAGE_W (BM * A_STRIDE)            // 5120 words
#define B_STAGE_W (BK * B_STRIDE)            // 2176 words
#define STAGE_W (A_STAGE_W + B_STAGE_W)      // 7296 words
#define EPI_STRIDE 66
#define SMEM_GEMM_BYTES (8 * 64 * EPI_STRIDE * 4)   // 135168 (> 2*STAGE_W*4 = 58368)

template <int KDIM, int NDIM, bool FIRST>
__global__ __launch_bounds__(256) void moe_gemm_kernel(
    const float* __restrict__ A,     // x when FIRST (g_h otherwise)
    const float* __restrict__ B,     // w1 / w2  [E, KDIM, NDIM]
    const float* __restrict__ bias,  // [E, NDIM]
    float* __restrict__ out)
{
    const int e = blockIdx.z;
    const int cnt = g_count[e];
    const int m0 = blockIdx.y * BM;
    if (m0 >= cnt) return;
    const int base = g_offset[e];
    const int n0 = blockIdx.x * BN;

    extern __shared__ unsigned dsm[];
    __shared__ int stok[BM];

    const int tid  = threadIdx.x;
    const int wid  = tid >> 5;
    const int lane = tid & 31;
    const int gq = lane >> 2;   // 0..7
    const int tg = lane & 3;    // 0..3
    const int wm = wid >> 1;    // 0..3 (64-row band)
    const int wn = wid & 1;     // 0..1 (64-col band)

    if (FIRST) {
#pragma unroll
        for (int j = tid; j < BM; j += 256) {
            int r = m0 + j;
            stok[j] = (r < cnt) ? g_slot_token[base + r] : -1;
        }
    }
    __syncthreads();

    const float* Ap = FIRST ? A : (const float*)g_h;
    const float* Bp = B + (size_t)e * KDIM * NDIM;

    // staging thread mappings
    const int a_r = tid >> 2;            // row within 64-row round
    const int a_c = (tid & 3) * 4;       // k offset (0,4,8,12)
    const int b_r = tid >> 4;            // B row 0..15
    const int b_c = (tid & 15) * 4;      // B col 0..60

    float acc[4][8][4];
#pragma unroll
    for (int mi = 0; mi < 4; mi++)
#pragma unroll
        for (int ni = 0; ni < 8; ni++)
#pragma unroll
            for (int r = 0; r < 4; r++) acc[mi][ni][r] = 0.0f;

    // ---- load a k-tile from gmem into regs ----
    float4 la[4], lb[2];
    auto load_tile = [&](int k0) {
#pragma unroll
        for (int ro = 0; ro < 4; ro++) {
            int m = ro * 64 + a_r;
            la[ro] = make_float4(0.f, 0.f, 0.f, 0.f);
            if (FIRST) {
                int tk = stok[m];
                if (tk >= 0)
                    la[ro] = *reinterpret_cast<const float4*>(
                        Ap + (size_t)tk * KDIM + k0 + a_c);
            } else {
                if (m0 + m < cnt)
                    la[ro] = *reinterpret_cast<const float4*>(
                        Ap + (size_t)(base + m0 + m) * KDIM + k0 + a_c);
            }
        }
        const float* brow = Bp + (size_t)(k0 + b_r) * NDIM + n0 + b_c;
        lb[0] = *reinterpret_cast<const float4*>(brow);
        lb[1] = *reinterpret_cast<const float4*>(brow + 64);
    };

    auto store_tile = [&](unsigned* As, unsigned* Bs) {
#pragma unroll
        for (int ro = 0; ro < 4; ro++) {
            int m = ro * 64 + a_r;
            uint4 t;
            t.x = tf32_rna(la[ro].x); t.y = tf32_rna(la[ro].y);
            t.z = tf32_rna(la[ro].z); t.w = tf32_rna(la[ro].w);
            *reinterpret_cast<uint4*>(&As[m * A_STRIDE + a_c]) = t;
        }
        uint4 t0, t1;
        t0.x = tf32_rna(lb[0].x); t0.y = tf32_rna(lb[0].y);
        t0.z = tf32_rna(lb[0].z); t0.w = tf32_rna(lb[0].w);
        t1.x = tf32_rna(lb[1].x); t1.y = tf32_rna(lb[1].y);
        t1.z = tf32_rna(lb[1].z); t1.w = tf32_rna(lb[1].w);
        *reinterpret_cast<uint4*>(&Bs[b_r * B_STRIDE + b_c]) = t0;
        *reinterpret_cast<uint4*>(&Bs[b_r * B_STRIDE + 64 + b_c]) = t1;
    };

    // ---- prologue ----
    load_tile(0);
    store_tile(dsm, dsm + A_STAGE_W);
    __syncthreads();

    const int KT = KDIM / BK;
    for (int kt = 0; kt < KT; kt++) {
        const int cur = kt & 1;
        const int nxt = cur ^ 1;
        unsigned* As = dsm + cur * STAGE_W;
        unsigned* Bs = As + A_STAGE_W;

        if (kt + 1 < KT) load_tile((kt + 1) * BK);

#pragma unroll
        for (int kk = 0; kk < BK; kk += 8) {
            unsigned afr[4][4], bfr[8][2];
#pragma unroll
            for (int mi = 0; mi < 4; mi++) {
                int r0 = wm * 64 + mi * 16 + gq;
                afr[mi][0] = As[r0 * A_STRIDE + kk + tg];
                afr[mi][1] = As[(r0 + 8) * A_STRIDE + kk + tg];
                afr[mi][2] = As[r0 * A_STRIDE + kk + tg + 4];
                afr[mi][3] = As[(r0 + 8) * A_STRIDE + kk + tg + 4];
            }
#pragma unroll
            for (int ni = 0; ni < 8; ni++) {
                int c0 = wn * 64 + ni * 8 + gq;
                bfr[ni][0] = Bs[(kk + tg) * B_STRIDE + c0];
                bfr[ni][1] = Bs[(kk + tg + 4) * B_STRIDE + c0];
            }
#pragma unroll
            for (int mi = 0; mi < 4; mi++)
#pragma unroll
                for (int ni = 0; ni < 8; ni++)
                    mma_tf32(acc[mi][ni], afr[mi], bfr[ni]);
        }

        if (kt + 1 < KT)
            store_tile(dsm + nxt * STAGE_W, dsm + nxt * STAGE_W + A_STAGE_W);
        __syncthreads();
    }

    // ---- epilogue: per-warp 64x64 smem transpose, coalesced global writes ----
    float* scr = reinterpret_cast<float*>(dsm) + wid * 64 * EPI_STRIDE;
#pragma unroll
    for (int mi = 0; mi < 4; mi++)
#pragma unroll
        for (int ni = 0; ni < 8; ni++)
#pragma unroll
            for (int r = 0; r < 4; r++) {
                int rr = mi * 16 + gq + ((r >= 2) ? 8 : 0);
                int cc = ni * 8 + 2 * tg + (r & 1);
                scr[rr * EPI_STRIDE + cc] = acc[mi][ni][r];
            }
    __syncwarp();

    const int gcol = n0 + wn * 64 + 2 * lane;
    float2 bv = *reinterpret_cast<const float2*>(bias + (size_t)e * NDIM + gcol);

#pragma unroll 4
    for (int rr = 0; rr < 64; rr++) {
        int slot = m0 + wm * 64 + rr;
        if (slot < cnt) {
            float2 v = *reinterpret_cast<const float2*>(&scr[rr * EPI_STRIDE + 2 * lane]);
            v.x += bv.x; v.y += bv.y;
            if (FIRST) {
                v.x = fmaxf(v.x, 0.0f); v.y = fmaxf(v.y, 0.0f);
                *reinterpret_cast<float2*>(
                    g_h + (size_t)(base + slot) * NDIM + gcol) = v;
            } else {
                float wg = g_slot_weight[base + slot];
                int   tk = g_slot_token[base + slot];
                atomicAdd(out + (size_t)tk * NDIM + gcol,     wg * v.x);
                atomicAdd(out + (size_t)tk * NDIM + gcol + 1, wg * v.y);
            }
        }
    }
}

// ---------------- launch ----------------
extern "C" void kernel_launch(void* const* d_in, const int* in_sizes, int n_in,
                              void* d_out, int out_size) {
    (void)in_sizes; (void)n_in;
    const float* x  = (const float*)d_in[0];
    const float* gw = (const float*)d_in[1];
    const float* gb = (const float*)d_in[2];
    const float* w1 = (const float*)d_in[3];
    const float* b1 = (const float*)d_in[4];
    const float* w2 = (const float*)d_in[5];
    const float* b2 = (const float*)d_in[6];
    float* out = (float*)d_out;

    static bool attr_set = false;
    if (!attr_set) {
        cudaFuncSetAttribute(moe_gemm_kernel<DDIM, HDIM, true>,
                             cudaFuncAttributeMaxDynamicSharedMemorySize, SMEM_GEMM_BYTES);
        cudaFuncSetAttribute(moe_gemm_kernel<HDIM, ODIM, false>,
                             cudaFuncAttributeMaxDynamicSharedMemorySize, SMEM_GEMM_BYTES);
        attr_set = true;
    }

    cudaMemsetAsync(out, 0, (size_t)out_size * sizeof(float), 0);
    init_counts_kernel<<<1, 32>>>();
    gate_kernel<<<NTOK / 8, 256>>>(x, gw, gb);
    offsets_kernel<<<1, 32>>>();
    scatter_kernel<<<NTOK / 256, 256>>>();

    dim3 g1(HDIM / BN, NTOK / BM, NEXP);   // (32, 32, 8)
    moe_gemm_kernel<DDIM, HDIM, true><<<g1, 256, SMEM_GEMM_BYTES>>>(x, w1, b1, nullptr);

    dim3 g2(ODIM / BN, NTOK / BM, NEXP);   // (8, 32, 8)
    moe_gemm_kernel<HDIM, ODIM, false><<<g2, 256, SMEM_GEMM_BYTES>>>(nullptr, w2, b2, out);
}

// round 4
// speedup vs baseline: 2.6177x; 2.1121x over previous
#include <cuda_runtime.h>
#include <cuda_fp16.h>
#include <math.h>
#include <stdint.h>

// ---------------- problem constants ----------------
#define NTOK 8192
#define DDIM 1024
#define HDIM 4096
#define ODIM 1024
#define NEXP 8
#define TOPK 3
#define NSLOT (NTOK * TOPK)

// ---------------- static device scratch ----------------
__device__ int    g_count[NEXP];
__device__ int    g_offset[NEXP];
__device__ int    g_cursor[NEXP];
__device__ int    g_topk_e[NTOK * TOPK];
__device__ float  g_topk_w[NTOK * TOPK];
__device__ int    g_slot_token[NSLOT];
__device__ float  g_slot_weight[NSLOT];
__device__ __half g_h[(size_t)NSLOT * HDIM];   // 201.3 MB (fp16 h activations)

// ---------------- helpers ----------------
__device__ __forceinline__ uint32_t smem_u32(const void* p) {
    uint32_t a;
    asm("{ .reg .u64 t; cvta.to.shared.u64 t, %1; cvt.u32.u64 %0, t; }"
        : "=r"(a) : "l"(p));
    return a;
}

__device__ __forceinline__ uint32_t pack_h2(float lo, float hi) {
    __half2 h = __floats2half2_rn(lo, hi);
    return *reinterpret_cast<uint32_t*>(&h);
}

__device__ __forceinline__ void ldsm_x4(uint32_t addr, uint32_t& r0, uint32_t& r1,
                                        uint32_t& r2, uint32_t& r3) {
    asm volatile("ldmatrix.sync.aligned.m8n8.x4.shared.b16 {%0,%1,%2,%3}, [%4];"
                 : "=r"(r0), "=r"(r1), "=r"(r2), "=r"(r3) : "r"(addr));
}

__device__ __forceinline__ void ldsm_x4_t(uint32_t addr, uint32_t& r0, uint32_t& r1,
                                          uint32_t& r2, uint32_t& r3) {
    asm volatile("ldmatrix.sync.aligned.m8n8.x4.trans.shared.b16 {%0,%1,%2,%3}, [%4];"
                 : "=r"(r0), "=r"(r1), "=r"(r2), "=r"(r3) : "r"(addr));
}

__device__ __forceinline__ void mma_f16(float* d, const uint32_t* a, const uint32_t* b) {
    asm volatile(
        "mma.sync.aligned.m16n8k16.row.col.f32.f16.f16.f32 "
        "{%0,%1,%2,%3}, {%4,%5,%6,%7}, {%8,%9}, {%0,%1,%2,%3};\n"
        : "+f"(d[0]), "+f"(d[1]), "+f"(d[2]), "+f"(d[3])
        : "r"(a[0]), "r"(a[1]), "r"(a[2]), "r"(a[3]),
          "r"(b[0]), "r"(b[1]));
}

// ---------------- init / gate / offsets / scatter (known-good) ----------------
__global__ void init_counts_kernel() {
    if (threadIdx.x < NEXP) g_count[threadIdx.x] = 0;
}

__global__ void gate_kernel(const float* __restrict__ x,
                            const float* __restrict__ gw,
                            const float* __restrict__ gb) {
    int tok  = (blockIdx.x * blockDim.x + threadIdx.x) >> 5;
    int lane = threadIdx.x & 31;
    if (tok >= NTOK) return;

    const float* xr = x + (size_t)tok * DDIM;
    float part[NEXP];
#pragma unroll
    for (int e = 0; e < NEXP; e++) part[e] = 0.0f;

#pragma unroll 4
    for (int j = 0; j < DDIM / 32; j++) {
        int d = j * 32 + lane;
        float xv = xr[d];
        const float4* gp = reinterpret_cast<const float4*>(gw + (size_t)d * NEXP);
        float4 a = gp[0];
        float4 b = gp[1];
        part[0] += xv * a.x; part[1] += xv * a.y;
        part[2] += xv * a.z; part[3] += xv * a.w;
        part[4] += xv * b.x; part[5] += xv * b.y;
        part[6] += xv * b.z; part[7] += xv * b.w;
    }
#pragma unroll
    for (int off = 16; off > 0; off >>= 1)
#pragma unroll
        for (int e = 0; e < NEXP; e++)
            part[e] += __shfl_xor_sync(0xffffffffu, part[e], off);

    if (lane == 0) {
        float s[NEXP];
#pragma unroll
        for (int e = 0; e < NEXP; e++) s[e] = part[e] + gb[e];

        int id[TOPK];
        bool used[NEXP];
#pragma unroll
        for (int e = 0; e < NEXP; e++) used[e] = false;
#pragma unroll
        for (int k = 0; k < TOPK; k++) {
            float best = -1e30f;
            int bi = 0;
#pragma unroll
            for (int e = 0; e < NEXP; e++)
                if (!used[e] && s[e] > best) { best = s[e]; bi = e; }
            used[bi] = true;
            id[k] = bi;
        }

        float mx = s[0];
#pragma unroll
        for (int e = 1; e < NEXP; e++) mx = fmaxf(mx, s[e]);
        float p[NEXP], tot = 0.0f;
#pragma unroll
        for (int e = 0; e < NEXP; e++) { p[e] = expf(s[e] - mx); tot += p[e]; }
        float inv = 1.0f / tot;
        float msum = (p[id[0]] + p[id[1]] + p[id[2]]) * inv;
        float den = msum + 1e-8f;

#pragma unroll
        for (int k = 0; k < TOPK; k++) {
            int e = id[k];
            g_topk_e[tok * TOPK + k] = e;
            g_topk_w[tok * TOPK + k] = (p[e] * inv) / den;
            atomicAdd(&g_count[e], 1);
        }
    }
}

__global__ void offsets_kernel() {
    if (threadIdx.x == 0 && blockIdx.x == 0) {
        int off = 0;
#pragma unroll
        for (int e = 0; e < NEXP; e++) {
            g_offset[e] = off;
            off += g_count[e];
            g_cursor[e] = 0;
        }
    }
}

__global__ void scatter_kernel() {
    int t = blockIdx.x * blockDim.x + threadIdx.x;
    if (t >= NTOK) return;
#pragma unroll
    for (int k = 0; k < TOPK; k++) {
        int e = g_topk_e[t * TOPK + k];
        int pos = atomicAdd(&g_cursor[e], 1);
        int i = g_offset[e] + pos;
        g_slot_token[i] = t;
        g_slot_weight[i] = g_topk_w[t * TOPK + k];
    }
}

// ---------------- fp16 mma.sync grouped GEMM ----------------
// CTA 256x128, 8 warps of 64x64, K-tile 32, double-buffered, ldmatrix fragments.
// A smem [m][k] stride 40 halves (conflict-free ldmatrix + staging).
// B smem [k][n] stride 136 halves (natural from gmem; ldmatrix.trans).
#define BM 256
#define BN 128
#define BK 32
#define SA 40     // A row stride (halves)
#define SB 136    // B row stride (halves)
#define A_STAGE_B (BM * SA * 2)              // 20480 bytes
#define B_STAGE_B (BK * SB * 2)              // 8704 bytes
#define STAGE_B (A_STAGE_B + B_STAGE_B)      // 29184 bytes
#define EPI_STRIDE 66
#define SMEM_GEMM_BYTES (8 * 64 * EPI_STRIDE * 4)   // 135168 (> 2*STAGE_B)

template <int KDIM, int NDIM, bool FIRST>
__global__ __launch_bounds__(256) void moe_gemm_kernel(
    const float* __restrict__ A,     // x when FIRST (g_h otherwise)
    const float* __restrict__ B,     // w1 / w2  [E, KDIM, NDIM]
    const float* __restrict__ bias,  // [E, NDIM]
    float* __restrict__ out)
{
    const int e = blockIdx.z;
    const int cnt = g_count[e];
    const int m0 = blockIdx.y * BM;
    if (m0 >= cnt) return;
    const int base = g_offset[e];
    const int n0 = blockIdx.x * BN;

    extern __shared__ char dsm[];
    __shared__ int stok[BM];
    const uint32_t sb = smem_u32(dsm);

    const int tid  = threadIdx.x;
    const int wid  = tid >> 5;
    const int lane = tid & 31;
    const int gq = lane >> 2;   // 0..7
    const int tg = lane & 3;    // 0..3
    const int wm = wid >> 1;    // 0..3
    const int wn = wid & 1;     // 0..1

    if (FIRST) {
#pragma unroll
        for (int j = tid; j < BM; j += 256) {
            int r = m0 + j;
            stok[j] = (r < cnt) ? g_slot_token[base + r] : -1;
        }
    }
    __syncthreads();

    const float*  Apf = A;
    const __half* Aph = g_h;
    const float*  Bp  = B + (size_t)e * KDIM * NDIM;

    // staging maps
    const int a_r1 = tid >> 3;            // FIRST: row in 32-row group
    const int a_c1 = (tid & 7) * 4;       // FIRST: k offset
    const int a_r2 = tid >> 2;            // !FIRST: row in 64-row group
    const int a_c2 = (tid & 3) * 8;       // !FIRST: k offset (halves)
    const int b_r  = tid >> 4;            // 0..15
    const int b_c  = (tid & 15) * 4;      // 0..60

    // ldmatrix lane offsets (bytes within stage)
    const uint32_t a_lm = (uint32_t)(((wm * 64 + (lane & 15)) * SA + ((lane >> 4) << 3)) * 2);
    const uint32_t b_lm = (uint32_t)(((lane & 15) * SB + wn * 64 + ((lane >> 4) << 3)) * 2);

    float acc[4][8][4];
#pragma unroll
    for (int mi = 0; mi < 4; mi++)
#pragma unroll
        for (int ni = 0; ni < 8; ni++)
#pragma unroll
            for (int r = 0; r < 4; r++) acc[mi][ni][r] = 0.0f;

    // staging registers
    float4 la1[8];    // FIRST
    uint4  la2[4];    // !FIRST
    float4 lb[2][2];  // B: 2 k-rounds x 2 col-halves

    auto load_tile = [&](int k0) {
        if (FIRST) {
#pragma unroll
            for (int ro = 0; ro < 8; ro++) {
                int m = ro * 32 + a_r1;
                la1[ro] = make_float4(0.f, 0.f, 0.f, 0.f);
                int tk = stok[m];
                if (tk >= 0)
                    la1[ro] = *reinterpret_cast<const float4*>(
                        Apf + (size_t)tk * KDIM + k0 + a_c1);
            }
        } else {
#pragma unroll
            for (int ro = 0; ro < 4; ro++) {
                int m = ro * 64 + a_r2;
                la2[ro] = make_uint4(0u, 0u, 0u, 0u);
                if (m0 + m < cnt)
                    la2[ro] = *reinterpret_cast<const uint4*>(
                        Aph + (size_t)(base + m0 + m) * KDIM + k0 + a_c2);
            }
        }
#pragma unroll
        for (int ro = 0; ro < 2; ro++) {
            const float* brow = Bp + (size_t)(k0 + ro * 16 + b_r) * NDIM + n0 + b_c;
            lb[ro][0] = *reinterpret_cast<const float4*>(brow);
            lb[ro][1] = *reinterpret_cast<const float4*>(brow + 64);
        }
    };

    auto store_tile = [&](char* stage) {
        __half* As = reinterpret_cast<__half*>(stage);
        __half* Bs = reinterpret_cast<__half*>(stage + A_STAGE_B);
        if (FIRST) {
#pragma unroll
            for (int ro = 0; ro < 8; ro++) {
                int m = ro * 32 + a_r1;
                uint2 u;
                u.x = pack_h2(la1[ro].x, la1[ro].y);
                u.y = pack_h2(la1[ro].z, la1[ro].w);
                *reinterpret_cast<uint2*>(As + m * SA + a_c1) = u;
            }
        } else {
#pragma unroll
            for (int ro = 0; ro < 4; ro++) {
                int m = ro * 64 + a_r2;
                *reinterpret_cast<uint4*>(As + m * SA + a_c2) = la2[ro];
            }
        }
#pragma unroll
        for (int ro = 0; ro < 2; ro++) {
            int kl = ro * 16 + b_r;
#pragma unroll
            for (int h = 0; h < 2; h++) {
                uint2 u;
                u.x = pack_h2(lb[ro][h].x, lb[ro][h].y);
                u.y = pack_h2(lb[ro][h].z, lb[ro][h].w);
                *reinterpret_cast<uint2*>(Bs + kl * SB + h * 64 + b_c) = u;
            }
        }
    };

    // ---- prologue ----
    load_tile(0);
    store_tile(dsm);
    __syncthreads();

    const int KT = KDIM / BK;
    for (int kt = 0; kt < KT; kt++) {
        const int cur = kt & 1;
        const uint32_t a_base = sb + cur * STAGE_B + a_lm;
        const uint32_t b_base = sb + cur * STAGE_B + A_STAGE_B + b_lm;

        if (kt + 1 < KT) load_tile((kt + 1) * BK);

#pragma unroll
        for (int kk = 0; kk < BK; kk += 16) {
            uint32_t af[4][4], bf[8][2];
#pragma unroll
            for (int mi = 0; mi < 4; mi++)
                ldsm_x4(a_base + (uint32_t)((mi * 16 * SA + kk) * 2),
                        af[mi][0], af[mi][1], af[mi][2], af[mi][3]);
#pragma unroll
            for (int nj = 0; nj < 4; nj++)
                ldsm_x4_t(b_base + (uint32_t)((kk * SB + nj * 16) * 2),
                          bf[2 * nj][0], bf[2 * nj][1], bf[2 * nj + 1][0], bf[2 * nj + 1][1]);
#pragma unroll
            for (int mi = 0; mi < 4; mi++)
#pragma unroll
                for (int ni = 0; ni < 8; ni++)
                    mma_f16(acc[mi][ni], af[mi], bf[ni]);
        }

        if (kt + 1 < KT) store_tile(dsm + (cur ^ 1) * STAGE_B);
        __syncthreads();
    }

    // ---- epilogue: per-warp 64x64 smem transpose, coalesced writes ----
    float* scr = reinterpret_cast<float*>(dsm) + wid * 64 * EPI_STRIDE;
#pragma unroll
    for (int mi = 0; mi < 4; mi++)
#pragma unroll
        for (int ni = 0; ni < 8; ni++)
#pragma unroll
            for (int r = 0; r < 4; r++) {
                int rr = mi * 16 + gq + ((r >= 2) ? 8 : 0);
                int cc = ni * 8 + 2 * tg + (r & 1);
                scr[rr * EPI_STRIDE + cc] = acc[mi][ni][r];
            }
    __syncwarp();

    const int gcol = n0 + wn * 64 + 2 * lane;
    float2 bv = *reinterpret_cast<const float2*>(bias + (size_t)e * NDIM + gcol);

#pragma unroll 4
    for (int rr = 0; rr < 64; rr++) {
        int slot = m0 + wm * 64 + rr;
        if (slot < cnt) {
            float2 v = *reinterpret_cast<const float2*>(&scr[rr * EPI_STRIDE + 2 * lane]);
            v.x += bv.x; v.y += bv.y;
            if (FIRST) {
                __half2 hv = __floats2half2_rn(fmaxf(v.x, 0.0f), fmaxf(v.y, 0.0f));
                *reinterpret_cast<__half2*>(
                    g_h + (size_t)(base + slot) * NDIM + gcol) = hv;
            } else {
                float wg = g_slot_weight[base + slot];
                int   tk = g_slot_token[base + slot];
                atomicAdd(out + (size_t)tk * NDIM + gcol,     wg * v.x);
                atomicAdd(out + (size_t)tk * NDIM + gcol + 1, wg * v.y);
            }
        }
    }
}

// ---------------- launch ----------------
extern "C" void kernel_launch(void* const* d_in, const int* in_sizes, int n_in,
                              void* d_out, int out_size) {
    (void)in_sizes; (void)n_in;
    const float* x  = (const float*)d_in[0];
    const float* gw = (const float*)d_in[1];
    const float* gb = (const float*)d_in[2];
    const float* w1 = (const float*)d_in[3];
    const float* b1 = (const float*)d_in[4];
    const float* w2 = (const float*)d_in[5];
    const float* b2 = (const float*)d_in[6];
    float* out = (float*)d_out;

    static bool attr_set = false;
    if (!attr_set) {
        cudaFuncSetAttribute(moe_gemm_kernel<DDIM, HDIM, true>,
                             cudaFuncAttributeMaxDynamicSharedMemorySize, SMEM_GEMM_BYTES);
        cudaFuncSetAttribute(moe_gemm_kernel<HDIM, ODIM, false>,
                             cudaFuncAttributeMaxDynamicSharedMemorySize, SMEM_GEMM_BYTES);
        attr_set = true;
    }

    cudaMemsetAsync(out, 0, (size_t)out_size * sizeof(float), 0);
    init_counts_kernel<<<1, 32>>>();
    gate_kernel<<<NTOK / 8, 256>>>(x, gw, gb);
    offsets_kernel<<<1, 32>>>();
    scatter_kernel<<<NTOK / 256, 256>>>();

    dim3 g1(HDIM / BN, NTOK / BM, NEXP);   // (32, 32, 8)
    moe_gemm_kernel<DDIM, HDIM, true><<<g1, 256, SMEM_GEMM_BYTES>>>(x, w1, b1, nullptr);

    dim3 g2(ODIM / BN, NTOK / BM, NEXP);   // (8, 32, 8)
    moe_gemm_kernel<HDIM, ODIM, false><<<g2, 256, SMEM_GEMM_BYTES>>>(nullptr, w2, b2, out);
}

// round 5
// speedup vs baseline: 2.7002x; 1.0315x over previous
#include <cuda_runtime.h>
#include <cuda_fp16.h>
#include <math.h>
#include <stdint.h>

// ---------------- problem constants ----------------
#define NTOK 8192
#define DDIM 1024
#define HDIM 4096
#define ODIM 1024
#define NEXP 8
#define TOPK 3
#define NSLOT (NTOK * TOPK)

// ---------------- static device scratch ----------------
__device__ int    g_count[NEXP];
__device__ int    g_offset[NEXP];
__device__ int    g_cursor[NEXP];
__device__ int    g_topk_e[NTOK * TOPK];
__device__ float  g_topk_w[NTOK * TOPK];
__device__ int    g_slot_token[NSLOT];
__device__ float  g_slot_weight[NSLOT];
__device__ __half g_h[(size_t)NSLOT * HDIM];   // 201.3 MB (fp16 h activations)

// ---------------- helpers ----------------
__device__ __forceinline__ uint32_t smem_u32(const void* p) {
    uint32_t a;
    asm("{ .reg .u64 t; cvta.to.shared.u64 t, %1; cvt.u32.u64 %0, t; }"
        : "=r"(a) : "l"(p));
    return a;
}

__device__ __forceinline__ uint32_t pack_h2(float lo, float hi) {
    __half2 h = __floats2half2_rn(lo, hi);
    return *reinterpret_cast<uint32_t*>(&h);
}

__device__ __forceinline__ void ldsm_x4(uint32_t addr, uint32_t& r0, uint32_t& r1,
                                        uint32_t& r2, uint32_t& r3) {
    asm volatile("ldmatrix.sync.aligned.m8n8.x4.shared.b16 {%0,%1,%2,%3}, [%4];"
                 : "=r"(r0), "=r"(r1), "=r"(r2), "=r"(r3) : "r"(addr));
}

__device__ __forceinline__ void ldsm_x4_t(uint32_t addr, uint32_t& r0, uint32_t& r1,
                                          uint32_t& r2, uint32_t& r3) {
    asm volatile("ldmatrix.sync.aligned.m8n8.x4.trans.shared.b16 {%0,%1,%2,%3}, [%4];"
                 : "=r"(r0), "=r"(r1), "=r"(r2), "=r"(r3) : "r"(addr));
}

__device__ __forceinline__ void mma_f16(float* d, const uint32_t* a, const uint32_t* b) {
    asm volatile(
        "mma.sync.aligned.m16n8k16.row.col.f32.f16.f16.f32 "
        "{%0,%1,%2,%3}, {%4,%5,%6,%7}, {%8,%9}, {%0,%1,%2,%3};\n"
        : "+f"(d[0]), "+f"(d[1]), "+f"(d[2]), "+f"(d[3])
        : "r"(a[0]), "r"(a[1]), "r"(a[2]), "r"(a[3]),
          "r"(b[0]), "r"(b[1]));
}

// ---------------- init / gate / offsets / scatter (known-good) ----------------
__global__ void init_counts_kernel() {
    if (threadIdx.x < NEXP) g_count[threadIdx.x] = 0;
}

__global__ void gate_kernel(const float* __restrict__ x,
                            const float* __restrict__ gw,
                            const float* __restrict__ gb) {
    int tok  = (blockIdx.x * blockDim.x + threadIdx.x) >> 5;
    int lane = threadIdx.x & 31;
    if (tok >= NTOK) return;

    const float* xr = x + (size_t)tok * DDIM;
    float part[NEXP];
#pragma unroll
    for (int e = 0; e < NEXP; e++) part[e] = 0.0f;

#pragma unroll 4
    for (int j = 0; j < DDIM / 32; j++) {
        int d = j * 32 + lane;
        float xv = xr[d];
        const float4* gp = reinterpret_cast<const float4*>(gw + (size_t)d * NEXP);
        float4 a = gp[0];
        float4 b = gp[1];
        part[0] += xv * a.x; part[1] += xv * a.y;
        part[2] += xv * a.z; part[3] += xv * a.w;
        part[4] += xv * b.x; part[5] += xv * b.y;
        part[6] += xv * b.z; part[7] += xv * b.w;
    }
#pragma unroll
    for (int off = 16; off > 0; off >>= 1)
#pragma unroll
        for (int e = 0; e < NEXP; e++)
            part[e] += __shfl_xor_sync(0xffffffffu, part[e], off);

    if (lane == 0) {
        float s[NEXP];
#pragma unroll
        for (int e = 0; e < NEXP; e++) s[e] = part[e] + gb[e];

        int id[TOPK];
        bool used[NEXP];
#pragma unroll
        for (int e = 0; e < NEXP; e++) used[e] = false;
#pragma unroll
        for (int k = 0; k < TOPK; k++) {
            float best = -1e30f;
            int bi = 0;
#pragma unroll
            for (int e = 0; e < NEXP; e++)
                if (!used[e] && s[e] > best) { best = s[e]; bi = e; }
            used[bi] = true;
            id[k] = bi;
        }

        float mx = s[0];
#pragma unroll
        for (int e = 1; e < NEXP; e++) mx = fmaxf(mx, s[e]);
        float p[NEXP], tot = 0.0f;
#pragma unroll
        for (int e = 0; e < NEXP; e++) { p[e] = expf(s[e] - mx); tot += p[e]; }
        float inv = 1.0f / tot;
        float msum = (p[id[0]] + p[id[1]] + p[id[2]]) * inv;
        float den = msum + 1e-8f;

#pragma unroll
        for (int k = 0; k < TOPK; k++) {
            int e = id[k];
            g_topk_e[tok * TOPK + k] = e;
            g_topk_w[tok * TOPK + k] = (p[e] * inv) / den;
            atomicAdd(&g_count[e], 1);
        }
    }
}

__global__ void offsets_kernel() {
    if (threadIdx.x == 0 && blockIdx.x == 0) {
        int off = 0;
#pragma unroll
        for (int e = 0; e < NEXP; e++) {
            g_offset[e] = off;
            off += g_count[e];
            g_cursor[e] = 0;
        }
    }
}

__global__ void scatter_kernel() {
    int t = blockIdx.x * blockDim.x + threadIdx.x;
    if (t >= NTOK) return;
#pragma unroll
    for (int k = 0; k < TOPK; k++) {
        int e = g_topk_e[t * TOPK + k];
        int pos = atomicAdd(&g_cursor[e], 1);
        int i = g_offset[e] + pos;
        g_slot_token[i] = t;
        g_slot_weight[i] = g_topk_w[t * TOPK + k];
    }
}

// ---------------- fp16 mma.sync grouped GEMM ----------------
// CTA 256x128, 8 warps of 64x64, K-tile 32, double-buffered, ldmatrix fragments.
// Mainloop schedules STS of the next stage UNDER the last mma chunk so the
// tensor pipe never idles on the staging path (only the barrier remains).
#define BM 256
#define BN 128
#define BK 32
#define SA 40     // A row stride (halves)
#define SB 136    // B row stride (halves)
#define A_STAGE_B (BM * SA * 2)              // 20480 bytes
#define B_STAGE_B (BK * SB * 2)              // 8704 bytes
#define STAGE_B (A_STAGE_B + B_STAGE_B)      // 29184 bytes
#define EPI_STRIDE 66
#define SMEM_GEMM_BYTES (8 * 64 * EPI_STRIDE * 4)   // 135168 (> 2*STAGE_B)

template <int KDIM, int NDIM, bool FIRST>
__global__ __launch_bounds__(256) void moe_gemm_kernel(
    const float* __restrict__ A,     // x when FIRST (g_h otherwise)
    const float* __restrict__ B,     // w1 / w2  [E, KDIM, NDIM]
    const float* __restrict__ bias,  // [E, NDIM]
    float* __restrict__ out)
{
    const int e = blockIdx.z;
    const int cnt = g_count[e];
    const int m0 = blockIdx.y * BM;
    if (m0 >= cnt) return;
    const int base = g_offset[e];
    const int n0 = blockIdx.x * BN;

    extern __shared__ char dsm[];
    __shared__ int stok[BM];
    const uint32_t sb = smem_u32(dsm);

    const int tid  = threadIdx.x;
    const int wid  = tid >> 5;
    const int lane = tid & 31;
    const int gq = lane >> 2;   // 0..7
    const int tg = lane & 3;    // 0..3
    const int wm = wid >> 1;    // 0..3
    const int wn = wid & 1;     // 0..1

    if (FIRST) {
#pragma unroll
        for (int j = tid; j < BM; j += 256) {
            int r = m0 + j;
            stok[j] = (r < cnt) ? g_slot_token[base + r] : -1;
        }
    }
    __syncthreads();

    const float*  Apf = A;
    const __half* Aph = g_h;
    const float*  Bp  = B + (size_t)e * KDIM * NDIM;

    // staging maps
    const int a_r1 = tid >> 3;            // FIRST: row in 32-row group
    const int a_c1 = (tid & 7) * 4;       // FIRST: k offset
    const int a_r2 = tid >> 2;            // !FIRST: row in 64-row group
    const int a_c2 = (tid & 3) * 8;       // !FIRST: k offset (halves)
    const int b_r  = tid >> 4;            // 0..15
    const int b_c  = (tid & 15) * 4;      // 0..60

    // ldmatrix lane offsets (bytes within stage)
    const uint32_t a_lm = (uint32_t)(((wm * 64 + (lane & 15)) * SA + ((lane >> 4) << 3)) * 2);
    const uint32_t b_lm = (uint32_t)(((lane & 15) * SB + wn * 64 + ((lane >> 4) << 3)) * 2);

    float acc[4][8][4];
#pragma unroll
    for (int mi = 0; mi < 4; mi++)
#pragma unroll
        for (int ni = 0; ni < 8; ni++)
#pragma unroll
            for (int r = 0; r < 4; r++) acc[mi][ni][r] = 0.0f;

    // staging registers
    float4 la1[8];    // FIRST
    uint4  la2[4];    // !FIRST
    float4 lb[2][2];  // B: 2 k-rounds x 2 col-halves

    auto load_tile = [&](int k0) {
        if (FIRST) {
#pragma unroll
            for (int ro = 0; ro < 8; ro++) {
                int m = ro * 32 + a_r1;
                la1[ro] = make_float4(0.f, 0.f, 0.f, 0.f);
                int tk = stok[m];
                if (tk >= 0)
                    la1[ro] = *reinterpret_cast<const float4*>(
                        Apf + (size_t)tk * KDIM + k0 + a_c1);
            }
        } else {
#pragma unroll
            for (int ro = 0; ro < 4; ro++) {
                int m = ro * 64 + a_r2;
                la2[ro] = make_uint4(0u, 0u, 0u, 0u);
                if (m0 + m < cnt)
                    la2[ro] = *reinterpret_cast<const uint4*>(
                        Aph + (size_t)(base + m0 + m) * KDIM + k0 + a_c2);
            }
        }
#pragma unroll
        for (int ro = 0; ro < 2; ro++) {
            const float* brow = Bp + (size_t)(k0 + ro * 16 + b_r) * NDIM + n0 + b_c;
            lb[ro][0] = *reinterpret_cast<const float4*>(brow);
            lb[ro][1] = *reinterpret_cast<const float4*>(brow + 64);
        }
    };

    auto store_tile = [&](char* stage) {
        __half* As = reinterpret_cast<__half*>(stage);
        __half* Bs = reinterpret_cast<__half*>(stage + A_STAGE_B);
        if (FIRST) {
#pragma unroll
            for (int ro = 0; ro < 8; ro++) {
                int m = ro * 32 + a_r1;
                uint2 u;
                u.x = pack_h2(la1[ro].x, la1[ro].y);
                u.y = pack_h2(la1[ro].z, la1[ro].w);
                *reinterpret_cast<uint2*>(As + m * SA + a_c1) = u;
            }
        } else {
#pragma unroll
            for (int ro = 0; ro < 4; ro++) {
                int m = ro * 64 + a_r2;
                *reinterpret_cast<uint4*>(As + m * SA + a_c2) = la2[ro];
            }
        }
#pragma unroll
        for (int ro = 0; ro < 2; ro++) {
            int kl = ro * 16 + b_r;
#pragma unroll
            for (int h = 0; h < 2; h++) {
                uint2 u;
                u.x = pack_h2(lb[ro][h].x, lb[ro][h].y);
                u.y = pack_h2(lb[ro][h].z, lb[ro][h].w);
                *reinterpret_cast<uint2*>(Bs + kl * SB + h * 64 + b_c) = u;
            }
        }
    };

    // ---- prologue ----
    load_tile(0);
    store_tile(dsm);
    __syncthreads();

    const int KT = KDIM / BK;
    for (int kt = 0; kt < KT; kt++) {
        const int cur = kt & 1;
        const uint32_t a_base = sb + cur * STAGE_B + a_lm;
        const uint32_t b_base = sb + cur * STAGE_B + A_STAGE_B + b_lm;
        const bool more = (kt + 1 < KT);

        // issue next tile's global loads first (latency covered by kk=0 mmas)
        if (more) load_tile((kt + 1) * BK);

        uint32_t af[4][4], bf[8][2];

        // ---- kk = 0 chunk: ldmatrix + 32 mma ----
#pragma unroll
        for (int mi = 0; mi < 4; mi++)
            ldsm_x4(a_base + (uint32_t)((mi * 16 * SA) * 2),
                    af[mi][0], af[mi][1], af[mi][2], af[mi][3]);
#pragma unroll
        for (int nj = 0; nj < 4; nj++)
            ldsm_x4_t(b_base + (uint32_t)((nj * 16) * 2),
                      bf[2 * nj][0], bf[2 * nj][1], bf[2 * nj + 1][0], bf[2 * nj + 1][1]);
#pragma unroll
        for (int mi = 0; mi < 4; mi++)
#pragma unroll
            for (int ni = 0; ni < 8; ni++)
                mma_f16(acc[mi][ni], af[mi], bf[ni]);

        // ---- kk = 16 chunk: ldmatrix first, then STS of next stage, then mma ----
        // The 32 trailing mmas cover the STS drain; only the barrier remains exposed.
#pragma unroll
        for (int mi = 0; mi < 4; mi++)
            ldsm_x4(a_base + (uint32_t)((mi * 16 * SA + 16) * 2),
                    af[mi][0], af[mi][1], af[mi][2], af[mi][3]);
#pragma unroll
        for (int nj = 0; nj < 4; nj++)
            ldsm_x4_t(b_base + (uint32_t)((16 * SB + nj * 16) * 2),
                      bf[2 * nj][0], bf[2 * nj][1], bf[2 * nj + 1][0], bf[2 * nj + 1][1]);

        if (more) store_tile(dsm + (cur ^ 1) * STAGE_B);

#pragma unroll
        for (int mi = 0; mi < 4; mi++)
#pragma unroll
            for (int ni = 0; ni < 8; ni++)
                mma_f16(acc[mi][ni], af[mi], bf[ni]);

        __syncthreads();
    }

    // ---- epilogue: per-warp 64x64 smem transpose, coalesced writes ----
    float* scr = reinterpret_cast<float*>(dsm) + wid * 64 * EPI_STRIDE;
#pragma unroll
    for (int mi = 0; mi < 4; mi++)
#pragma unroll
        for (int ni = 0; ni < 8; ni++)
#pragma unroll
            for (int r = 0; r < 4; r++) {
                int rr = mi * 16 + gq + ((r >= 2) ? 8 : 0);
                int cc = ni * 8 + 2 * tg + (r & 1);
                scr[rr * EPI_STRIDE + cc] = acc[mi][ni][r];
            }
    __syncwarp();

    const int gcol = n0 + wn * 64 + 2 * lane;
    float2 bv = *reinterpret_cast<const float2*>(bias + (size_t)e * NDIM + gcol);

#pragma unroll 4
    for (int rr = 0; rr < 64; rr++) {
        int slot = m0 + wm * 64 + rr;
        if (slot < cnt) {
            float2 v = *reinterpret_cast<const float2*>(&scr[rr * EPI_STRIDE + 2 * lane]);
            v.x += bv.x; v.y += bv.y;
            if (FIRST) {
                __half2 hv = __floats2half2_rn(fmaxf(v.x, 0.0f), fmaxf(v.y, 0.0f));
                *reinterpret_cast<__half2*>(
                    g_h + (size_t)(base + slot) * NDIM + gcol) = hv;
            } else {
                float wg = g_slot_weight[base + slot];
                int   tk = g_slot_token[base + slot];
                atomicAdd(out + (size_t)tk * NDIM + gcol,     wg * v.x);
                atomicAdd(out + (size_t)tk * NDIM + gcol + 1, wg * v.y);
            }
        }
    }
}

// ---------------- launch ----------------
extern "C" void kernel_launch(void* const* d_in, const int* in_sizes, int n_in,
                              void* d_out, int out_size) {
    (void)in_sizes; (void)n_in;
    const float* x  = (const float*)d_in[0];
    const float* gw = (const float*)d_in[1];
    const float* gb = (const float*)d_in[2];
    const float* w1 = (const float*)d_in[3];
    const float* b1 = (const float*)d_in[4];
    const float* w2 = (const float*)d_in[5];
    const float* b2 = (const float*)d_in[6];
    float* out = (float*)d_out;

    static bool attr_set = false;
    if (!attr_set) {
        cudaFuncSetAttribute(moe_gemm_kernel<DDIM, HDIM, true>,
                             cudaFuncAttributeMaxDynamicSharedMemorySize, SMEM_GEMM_BYTES);
        cudaFuncSetAttribute(moe_gemm_kernel<HDIM, ODIM, false>,
                             cudaFuncAttributeMaxDynamicSharedMemorySize, SMEM_GEMM_BYTES);
        attr_set = true;
    }

    cudaMemsetAsync(out, 0, (size_t)out_size * sizeof(float), 0);
    init_counts_kernel<<<1, 32>>>();
    gate_kernel<<<NTOK / 8, 256>>>(x, gw, gb);
    offsets_kernel<<<1, 32>>>();
    scatter_kernel<<<NTOK / 256, 256>>>();

    dim3 g1(HDIM / BN, NTOK / BM, NEXP);   // (32, 32, 8)
    moe_gemm_kernel<DDIM, HDIM, true><<<g1, 256, SMEM_GEMM_BYTES>>>(x, w1, b1, nullptr);

    dim3 g2(ODIM / BN, NTOK / BM, NEXP);   // (8, 32, 8)
    moe_gemm_kernel<HDIM, ODIM, false><<<g2, 256, SMEM_GEMM_BYTES>>>(nullptr, w2, b2, out);
}

// round 6
// speedup vs baseline: 2.8540x; 1.0570x over previous
#include <cuda_runtime.h>
#include <cuda_fp16.h>
#include <math.h>
#include <stdint.h>

// ---------------- problem constants ----------------
#define NTOK 8192
#define DDIM 1024
#define HDIM 4096
#define ODIM 1024
#define NEXP 8
#define TOPK 3
#define NSLOT (NTOK * TOPK)

// ---------------- static device scratch ----------------
__device__ int    g_count[NEXP];
__device__ int    g_offset[NEXP];
__device__ int    g_cursor[NEXP];
__device__ int    g_topk_e[NTOK * TOPK];
__device__ float  g_topk_w[NTOK * TOPK];
__device__ int    g_slot_token[NSLOT];
__device__ float  g_slot_weight[NSLOT];
__device__ __half g_h[(size_t)NSLOT * HDIM];   // 201.3 MB (fp16 h activations)

// ---------------- helpers ----------------
__device__ __forceinline__ uint32_t smem_u32(const void* p) {
    uint32_t a;
    asm("{ .reg .u64 t; cvta.to.shared.u64 t, %1; cvt.u32.u64 %0, t; }"
        : "=r"(a) : "l"(p));
    return a;
}

__device__ __forceinline__ uint32_t pack_h2(float lo, float hi) {
    __half2 h = __floats2half2_rn(lo, hi);
    return *reinterpret_cast<uint32_t*>(&h);
}

__device__ __forceinline__ void ldsm_x4(uint32_t addr, uint32_t& r0, uint32_t& r1,
                                        uint32_t& r2, uint32_t& r3) {
    asm volatile("ldmatrix.sync.aligned.m8n8.x4.shared.b16 {%0,%1,%2,%3}, [%4];"
                 : "=r"(r0), "=r"(r1), "=r"(r2), "=r"(r3) : "r"(addr));
}

__device__ __forceinline__ void ldsm_x4_t(uint32_t addr, uint32_t& r0, uint32_t& r1,
                                          uint32_t& r2, uint32_t& r3) {
    asm volatile("ldmatrix.sync.aligned.m8n8.x4.trans.shared.b16 {%0,%1,%2,%3}, [%4];"
                 : "=r"(r0), "=r"(r1), "=r"(r2), "=r"(r3) : "r"(addr));
}

__device__ __forceinline__ void mma_f16(float* d, const uint32_t* a, const uint32_t* b) {
    asm volatile(
        "mma.sync.aligned.m16n8k16.row.col.f32.f16.f16.f32 "
        "{%0,%1,%2,%3}, {%4,%5,%6,%7}, {%8,%9}, {%0,%1,%2,%3};\n"
        : "+f"(d[0]), "+f"(d[1]), "+f"(d[2]), "+f"(d[3])
        : "r"(a[0]), "r"(a[1]), "r"(a[2]), "r"(a[3]),
          "r"(b[0]), "r"(b[1]));
}

// ---------------- init / gate / offsets / scatter (known-good) ----------------
__global__ void init_counts_kernel() {
    if (threadIdx.x < NEXP) g_count[threadIdx.x] = 0;
}

__global__ void gate_kernel(const float* __restrict__ x,
                            const float* __restrict__ gw,
                            const float* __restrict__ gb) {
    int tok  = (blockIdx.x * blockDim.x + threadIdx.x) >> 5;
    int lane = threadIdx.x & 31;
    if (tok >= NTOK) return;

    const float* xr = x + (size_t)tok * DDIM;
    float part[NEXP];
#pragma unroll
    for (int e = 0; e < NEXP; e++) part[e] = 0.0f;

#pragma unroll 4
    for (int j = 0; j < DDIM / 32; j++) {
        int d = j * 32 + lane;
        float xv = xr[d];
        const float4* gp = reinterpret_cast<const float4*>(gw + (size_t)d * NEXP);
        float4 a = gp[0];
        float4 b = gp[1];
        part[0] += xv * a.x; part[1] += xv * a.y;
        part[2] += xv * a.z; part[3] += xv * a.w;
        part[4] += xv * b.x; part[5] += xv * b.y;
        part[6] += xv * b.z; part[7] += xv * b.w;
    }
#pragma unroll
    for (int off = 16; off > 0; off >>= 1)
#pragma unroll
        for (int e = 0; e < NEXP; e++)
            part[e] += __shfl_xor_sync(0xffffffffu, part[e], off);

    if (lane == 0) {
        float s[NEXP];
#pragma unroll
        for (int e = 0; e < NEXP; e++) s[e] = part[e] + gb[e];

        int id[TOPK];
        bool used[NEXP];
#pragma unroll
        for (int e = 0; e < NEXP; e++) used[e] = false;
#pragma unroll
        for (int k = 0; k < TOPK; k++) {
            float best = -1e30f;
            int bi = 0;
#pragma unroll
            for (int e = 0; e < NEXP; e++)
                if (!used[e] && s[e] > best) { best = s[e]; bi = e; }
            used[bi] = true;
            id[k] = bi;
        }

        float mx = s[0];
#pragma unroll
        for (int e = 1; e < NEXP; e++) mx = fmaxf(mx, s[e]);
        float p[NEXP], tot = 0.0f;
#pragma unroll
        for (int e = 0; e < NEXP; e++) { p[e] = expf(s[e] - mx); tot += p[e]; }
        float inv = 1.0f / tot;
        float msum = (p[id[0]] + p[id[1]] + p[id[2]]) * inv;
        float den = msum + 1e-8f;

#pragma unroll
        for (int k = 0; k < TOPK; k++) {
            int e = id[k];
            g_topk_e[tok * TOPK + k] = e;
            g_topk_w[tok * TOPK + k] = (p[e] * inv) / den;
            atomicAdd(&g_count[e], 1);
        }
    }
}

__global__ void offsets_kernel() {
    if (threadIdx.x == 0 && blockIdx.x == 0) {
        int off = 0;
#pragma unroll
        for (int e = 0; e < NEXP; e++) {
            g_offset[e] = off;
            off += g_count[e];
            g_cursor[e] = 0;
        }
    }
}

__global__ void scatter_kernel() {
    int t = blockIdx.x * blockDim.x + threadIdx.x;
    if (t >= NTOK) return;
#pragma unroll
    for (int k = 0; k < TOPK; k++) {
        int e = g_topk_e[t * TOPK + k];
        int pos = atomicAdd(&g_cursor[e], 1);
        int i = g_offset[e] + pos;
        g_slot_token[i] = t;
        g_slot_weight[i] = g_topk_w[t * TOPK + k];
    }
}

// ---------------- fp16 mma.sync grouped GEMM ----------------
// CTA 128x128, 4 warps of 64x64, K-tile 32, double-buffered, ldmatrix fragments.
// Small CTA + 67.6KB smem + <=256 regs -> 2 CTAs/SM: barriers/prologue/epilogue
// and wave tails overlap with the co-resident CTA's mma stream.
#define BM 128
#define BN 128
#define BK 32
#define SA 40     // A row stride (halves)
#define SB 136    // B row stride (halves)
#define A_STAGE_B (BM * SA * 2)              // 10240 bytes
#define B_STAGE_B (BK * SB * 2)              // 8704 bytes
#define STAGE_B (A_STAGE_B + B_STAGE_B)      // 18944 bytes
#define EPI_STRIDE 66
#define SMEM_GEMM_BYTES (4 * 64 * EPI_STRIDE * 4)   // 67584 (> 2*STAGE_B = 37888)

template <int KDIM, int NDIM, bool FIRST>
__global__ __launch_bounds__(128, 2) void moe_gemm_kernel(
    const float* __restrict__ A,     // x when FIRST (g_h otherwise)
    const float* __restrict__ B,     // w1 / w2  [E, KDIM, NDIM]
    const float* __restrict__ bias,  // [E, NDIM]
    float* __restrict__ out)
{
    const int e = blockIdx.z;
    const int cnt = g_count[e];
    const int m0 = blockIdx.y * BM;
    if (m0 >= cnt) return;
    const int base = g_offset[e];
    const int n0 = blockIdx.x * BN;

    extern __shared__ char dsm[];
    __shared__ int stok[BM];
    const uint32_t sb = smem_u32(dsm);

    const int tid  = threadIdx.x;
    const int wid  = tid >> 5;
    const int lane = tid & 31;
    const int gq = lane >> 2;   // 0..7
    const int tg = lane & 3;    // 0..3
    const int wm = wid >> 1;    // 0..1
    const int wn = wid & 1;     // 0..1

    if (FIRST) {
        if (tid < BM) {
            int r = m0 + tid;
            stok[tid] = (r < cnt) ? g_slot_token[base + r] : -1;
        }
    }
    __syncthreads();

    const float*  Apf = A;
    const __half* Aph = g_h;
    const float*  Bp  = B + (size_t)e * KDIM * NDIM;

    // staging maps (128 threads)
    const int a_r1 = tid >> 3;            // FIRST: row in 16-row group (0..15)
    const int a_c1 = (tid & 7) * 4;       // FIRST: k offset (floats)
    const int a_r2 = tid >> 2;            // !FIRST: row in 32-row group (0..31)
    const int a_c2 = (tid & 3) * 8;       // !FIRST: k offset (halves)
    const int b_r  = tid >> 4;            // 0..7
    const int b_c  = (tid & 15) * 4;      // 0..60

    // ldmatrix lane offsets (bytes within stage)
    const uint32_t a_lm = (uint32_t)(((wm * 64 + (lane & 15)) * SA + ((lane >> 4) << 3)) * 2);
    const uint32_t b_lm = (uint32_t)(((lane & 15) * SB + wn * 64 + ((lane >> 4) << 3)) * 2);

    float acc[4][8][4];
#pragma unroll
    for (int mi = 0; mi < 4; mi++)
#pragma unroll
        for (int ni = 0; ni < 8; ni++)
#pragma unroll
            for (int r = 0; r < 4; r++) acc[mi][ni][r] = 0.0f;

    // staging registers
    float4 la1[8];    // FIRST: 8 rounds x 16 rows
    uint4  la2[4];    // !FIRST: 4 rounds x 32 rows
    float4 lb[4][2];  // B: 4 k-rounds (8 rows) x 2 col-halves

    auto load_tile = [&](int k0) {
        if (FIRST) {
#pragma unroll
            for (int ro = 0; ro < 8; ro++) {
                int m = ro * 16 + a_r1;
                la1[ro] = make_float4(0.f, 0.f, 0.f, 0.f);
                int tk = stok[m];
                if (tk >= 0)
                    la1[ro] = *reinterpret_cast<const float4*>(
                        Apf + (size_t)tk * KDIM + k0 + a_c1);
            }
        } else {
#pragma unroll
            for (int ro = 0; ro < 4; ro++) {
                int m = ro * 32 + a_r2;
                la2[ro] = make_uint4(0u, 0u, 0u, 0u);
                if (m0 + m < cnt)
                    la2[ro] = *reinterpret_cast<const uint4*>(
                        Aph + (size_t)(base + m0 + m) * KDIM + k0 + a_c2);
            }
        }
#pragma unroll
        for (int ro = 0; ro < 4; ro++) {
            const float* brow = Bp + (size_t)(k0 + ro * 8 + b_r) * NDIM + n0 + b_c;
            lb[ro][0] = *reinterpret_cast<const float4*>(brow);
            lb[ro][1] = *reinterpret_cast<const float4*>(brow + 64);
        }
    };

    auto store_tile = [&](char* stage) {
        __half* As = reinterpret_cast<__half*>(stage);
        __half* Bs = reinterpret_cast<__half*>(stage + A_STAGE_B);
        if (FIRST) {
#pragma unroll
            for (int ro = 0; ro < 8; ro++) {
                int m = ro * 16 + a_r1;
                uint2 u;
                u.x = pack_h2(la1[ro].x, la1[ro].y);
                u.y = pack_h2(la1[ro].z, la1[ro].w);
                *reinterpret_cast<uint2*>(As + m * SA + a_c1) = u;
            }
        } else {
#pragma unroll
            for (int ro = 0; ro < 4; ro++) {
                int m = ro * 32 + a_r2;
                *reinterpret_cast<uint4*>(As + m * SA + a_c2) = la2[ro];
            }
        }
#pragma unroll
        for (int ro = 0; ro < 4; ro++) {
            int kl = ro * 8 + b_r;
#pragma unroll
            for (int h = 0; h < 2; h++) {
                uint2 u;
                u.x = pack_h2(lb[ro][h].x, lb[ro][h].y);
                u.y = pack_h2(lb[ro][h].z, lb[ro][h].w);
                *reinterpret_cast<uint2*>(Bs + kl * SB + h * 64 + b_c) = u;
            }
        }
    };

    // ---- prologue ----
    load_tile(0);
    store_tile(dsm);
    __syncthreads();

    const int KT = KDIM / BK;
    for (int kt = 0; kt < KT; kt++) {
        const int cur = kt & 1;
        const uint32_t a_base = sb + cur * STAGE_B + a_lm;
        const uint32_t b_base = sb + cur * STAGE_B + A_STAGE_B + b_lm;
        const bool more = (kt + 1 < KT);

        // issue next tile's global loads first (latency covered by kk=0 mmas)
        if (more) load_tile((kt + 1) * BK);

        uint32_t af[4][4], bf[8][2];

        // ---- kk = 0 chunk ----
#pragma unroll
        for (int mi = 0; mi < 4; mi++)
            ldsm_x4(a_base + (uint32_t)((mi * 16 * SA) * 2),
                    af[mi][0], af[mi][1], af[mi][2], af[mi][3]);
#pragma unroll
        for (int nj = 0; nj < 4; nj++)
            ldsm_x4_t(b_base + (uint32_t)((nj * 16) * 2),
                      bf[2 * nj][0], bf[2 * nj][1], bf[2 * nj + 1][0], bf[2 * nj + 1][1]);
#pragma unroll
        for (int mi = 0; mi < 4; mi++)
#pragma unroll
            for (int ni = 0; ni < 8; ni++)
                mma_f16(acc[mi][ni], af[mi], bf[ni]);

        // ---- kk = 16 chunk: ldmatrix, then STS of next stage, then mma ----
#pragma unroll
        for (int mi = 0; mi < 4; mi++)
            ldsm_x4(a_base + (uint32_t)((mi * 16 * SA + 16) * 2),
                    af[mi][0], af[mi][1], af[mi][2], af[mi][3]);
#pragma unroll
        for (int nj = 0; nj < 4; nj++)
            ldsm_x4_t(b_base + (uint32_t)((16 * SB + nj * 16) * 2),
                      bf[2 * nj][0], bf[2 * nj][1], bf[2 * nj + 1][0], bf[2 * nj + 1][1]);

        if (more) store_tile(dsm + (cur ^ 1) * STAGE_B);

#pragma unroll
        for (int mi = 0; mi < 4; mi++)
#pragma unroll
            for (int ni = 0; ni < 8; ni++)
                mma_f16(acc[mi][ni], af[mi], bf[ni]);

        __syncthreads();
    }

    // ---- epilogue: per-warp 64x64 smem transpose, coalesced writes ----
    float* scr = reinterpret_cast<float*>(dsm) + wid * 64 * EPI_STRIDE;
#pragma unroll
    for (int mi = 0; mi < 4; mi++)
#pragma unroll
        for (int ni = 0; ni < 8; ni++)
#pragma unroll
            for (int r = 0; r < 4; r++) {
                int rr = mi * 16 + gq + ((r >= 2) ? 8 : 0);
                int cc = ni * 8 + 2 * tg + (r & 1);
                scr[rr * EPI_STRIDE + cc] = acc[mi][ni][r];
            }
    __syncwarp();

    const int gcol = n0 + wn * 64 + 2 * lane;
    float2 bv = *reinterpret_cast<const float2*>(bias + (size_t)e * NDIM + gcol);

#pragma unroll 4
    for (int rr = 0; rr < 64; rr++) {
        int slot = m0 + wm * 64 + rr;
        if (slot < cnt) {
            float2 v = *reinterpret_cast<const float2*>(&scr[rr * EPI_STRIDE + 2 * lane]);
            v.x += bv.x; v.y += bv.y;
            if (FIRST) {
                __half2 hv = __floats2half2_rn(fmaxf(v.x, 0.0f), fmaxf(v.y, 0.0f));
                *reinterpret_cast<__half2*>(
                    g_h + (size_t)(base + slot) * NDIM + gcol) = hv;
            } else {
                float wg = g_slot_weight[base + slot];
                int   tk = g_slot_token[base + slot];
                atomicAdd(out + (size_t)tk * NDIM + gcol,     wg * v.x);
                atomicAdd(out + (size_t)tk * NDIM + gcol + 1, wg * v.y);
            }
        }
    }
}

// ---------------- launch ----------------
extern "C" void kernel_launch(void* const* d_in, const int* in_sizes, int n_in,
                              void* d_out, int out_size) {
    (void)in_sizes; (void)n_in;
    const float* x  = (const float*)d_in[0];
    const float* gw = (const float*)d_in[1];
    const float* gb = (const float*)d_in[2];
    const float* w1 = (const float*)d_in[3];
    const float* b1 = (const float*)d_in[4];
    const float* w2 = (const float*)d_in[5];
    const float* b2 = (const float*)d_in[6];
    float* out = (float*)d_out;

    static bool attr_set = false;
    if (!attr_set) {
        cudaFuncSetAttribute(moe_gemm_kernel<DDIM, HDIM, true>,
                             cudaFuncAttributeMaxDynamicSharedMemorySize, SMEM_GEMM_BYTES);
        cudaFuncSetAttribute(moe_gemm_kernel<HDIM, ODIM, false>,
                             cudaFuncAttributeMaxDynamicSharedMemorySize, SMEM_GEMM_BYTES);
        attr_set = true;
    }

    cudaMemsetAsync(out, 0, (size_t)out_size * sizeof(float), 0);
    init_counts_kernel<<<1, 32>>>();
    gate_kernel<<<NTOK / 8, 256>>>(x, gw, gb);
    offsets_kernel<<<1, 32>>>();
    scatter_kernel<<<NTOK / 256, 256>>>();

    dim3 g1(HDIM / BN, NTOK / BM, NEXP);   // (32, 64, 8)
    moe_gemm_kernel<DDIM, HDIM, true><<<g1, 128, SMEM_GEMM_BYTES>>>(x, w1, b1, nullptr);

    dim3 g2(ODIM / BN, NTOK / BM, NEXP);   // (8, 64, 8)
    moe_gemm_kernel<HDIM, ODIM, false><<<g2, 128, SMEM_GEMM_BYTES>>>(nullptr, w2, b2, out);
}

// round 7
// speedup vs baseline: 2.8849x; 1.0108x over previous
#include <cuda_runtime.h>
#include <cuda_fp16.h>
#include <math.h>
#include <stdint.h>

// ---------------- problem constants ----------------
#define NTOK 8192
#define DDIM 1024
#define HDIM 4096
#define ODIM 1024
#define NEXP 8
#define TOPK 3
#define NSLOT (NTOK * TOPK)

// ---------------- static device scratch ----------------
__device__ int    g_count[NEXP];
__device__ int    g_offset[NEXP];
__device__ int    g_cursor[NEXP];
__device__ int    g_topk_e[NTOK * TOPK];
__device__ float  g_topk_w[NTOK * TOPK];
__device__ int    g_slot_token[NSLOT];
__device__ float  g_slot_weight[NSLOT];
__device__ __half g_h[(size_t)NSLOT * HDIM];   // 201.3 MB (fp16 h activations)

// ---------------- helpers ----------------
__device__ __forceinline__ uint32_t smem_u32(const void* p) {
    uint32_t a;
    asm("{ .reg .u64 t; cvta.to.shared.u64 t, %1; cvt.u32.u64 %0, t; }"
        : "=r"(a) : "l"(p));
    return a;
}

__device__ __forceinline__ uint32_t pack_h2(float lo, float hi) {
    __half2 h = __floats2half2_rn(lo, hi);
    return *reinterpret_cast<uint32_t*>(&h);
}

__device__ __forceinline__ void ldsm_x4(uint32_t addr, uint32_t& r0, uint32_t& r1,
                                        uint32_t& r2, uint32_t& r3) {
    asm volatile("ldmatrix.sync.aligned.m8n8.x4.shared.b16 {%0,%1,%2,%3}, [%4];"
                 : "=r"(r0), "=r"(r1), "=r"(r2), "=r"(r3) : "r"(addr));
}

__device__ __forceinline__ void ldsm_x4_t(uint32_t addr, uint32_t& r0, uint32_t& r1,
                                          uint32_t& r2, uint32_t& r3) {
    asm volatile("ldmatrix.sync.aligned.m8n8.x4.trans.shared.b16 {%0,%1,%2,%3}, [%4];"
                 : "=r"(r0), "=r"(r1), "=r"(r2), "=r"(r3) : "r"(addr));
}

__device__ __forceinline__ void mma_f16(float* d, const uint32_t* a, const uint32_t* b) {
    asm volatile(
        "mma.sync.aligned.m16n8k16.row.col.f32.f16.f16.f32 "
        "{%0,%1,%2,%3}, {%4,%5,%6,%7}, {%8,%9}, {%0,%1,%2,%3};\n"
        : "+f"(d[0]), "+f"(d[1]), "+f"(d[2]), "+f"(d[3])
        : "r"(a[0]), "r"(a[1]), "r"(a[2]), "r"(a[3]),
          "r"(b[0]), "r"(b[1]));
}

// ---------------- init / gate / offsets / scatter (known-good) ----------------
__global__ void init_counts_kernel() {
    if (threadIdx.x < NEXP) g_count[threadIdx.x] = 0;
}

__global__ void gate_kernel(const float* __restrict__ x,
                            const float* __restrict__ gw,
                            const float* __restrict__ gb) {
    int tok  = (blockIdx.x * blockDim.x + threadIdx.x) >> 5;
    int lane = threadIdx.x & 31;
    if (tok >= NTOK) return;

    const float* xr = x + (size_t)tok * DDIM;
    float part[NEXP];
#pragma unroll
    for (int e = 0; e < NEXP; e++) part[e] = 0.0f;

#pragma unroll 4
    for (int j = 0; j < DDIM / 32; j++) {
        int d = j * 32 + lane;
        float xv = xr[d];
        const float4* gp = reinterpret_cast<const float4*>(gw + (size_t)d * NEXP);
        float4 a = gp[0];
        float4 b = gp[1];
        part[0] += xv * a.x; part[1] += xv * a.y;
        part[2] += xv * a.z; part[3] += xv * a.w;
        part[4] += xv * b.x; part[5] += xv * b.y;
        part[6] += xv * b.z; part[7] += xv * b.w;
    }
#pragma unroll
    for (int off = 16; off > 0; off >>= 1)
#pragma unroll
        for (int e = 0; e < NEXP; e++)
            part[e] += __shfl_xor_sync(0xffffffffu, part[e], off);

    if (lane == 0) {
        float s[NEXP];
#pragma unroll
        for (int e = 0; e < NEXP; e++) s[e] = part[e] + gb[e];

        int id[TOPK];
        bool used[NEXP];
#pragma unroll
        for (int e = 0; e < NEXP; e++) used[e] = false;
#pragma unroll
        for (int k = 0; k < TOPK; k++) {
            float best = -1e30f;
            int bi = 0;
#pragma unroll
            for (int e = 0; e < NEXP; e++)
                if (!used[e] && s[e] > best) { best = s[e]; bi = e; }
            used[bi] = true;
            id[k] = bi;
        }

        float mx = s[0];
#pragma unroll
        for (int e = 1; e < NEXP; e++) mx = fmaxf(mx, s[e]);
        float p[NEXP], tot = 0.0f;
#pragma unroll
        for (int e = 0; e < NEXP; e++) { p[e] = expf(s[e] - mx); tot += p[e]; }
        float inv = 1.0f / tot;
        float msum = (p[id[0]] + p[id[1]] + p[id[2]]) * inv;
        float den = msum + 1e-8f;

#pragma unroll
        for (int k = 0; k < TOPK; k++) {
            int e = id[k];
            g_topk_e[tok * TOPK + k] = e;
            g_topk_w[tok * TOPK + k] = (p[e] * inv) / den;
            atomicAdd(&g_count[e], 1);
        }
    }
}

__global__ void offsets_kernel() {
    if (threadIdx.x == 0 && blockIdx.x == 0) {
        int off = 0;
#pragma unroll
        for (int e = 0; e < NEXP; e++) {
            g_offset[e] = off;
            off += g_count[e];
            g_cursor[e] = 0;
        }
    }
}

__global__ void scatter_kernel() {
    int t = blockIdx.x * blockDim.x + threadIdx.x;
    if (t >= NTOK) return;
#pragma unroll
    for (int k = 0; k < TOPK; k++) {
        int e = g_topk_e[t * TOPK + k];
        int pos = atomicAdd(&g_cursor[e], 1);
        int i = g_offset[e] + pos;
        g_slot_token[i] = t;
        g_slot_weight[i] = g_topk_w[t * TOPK + k];
    }
}

// ---------------- fp16 mma.sync grouped GEMM ----------------
// CTA 128x128, 4 warps of 64x64, K-tile 32, double-buffered, ldmatrix fragments.
// occ=2 per SM. GEMM2 uses KSPLIT=2 (split-K): halves CTA duration -> halves
// the ragged-final-wave tail; partials combine via the existing atomicAdd path.
#define BM 128
#define BN 128
#define BK 32
#define SA 40     // A row stride (halves)
#define SB 136    // B row stride (halves)
#define A_STAGE_B (BM * SA * 2)              // 10240 bytes
#define B_STAGE_B (BK * SB * 2)              // 8704 bytes
#define STAGE_B (A_STAGE_B + B_STAGE_B)      // 18944 bytes
#define EPI_STRIDE 66
#define SMEM_GEMM_BYTES (4 * 64 * EPI_STRIDE * 4)   // 67584 (> 2*STAGE_B = 37888)

template <int KDIM, int NDIM, bool FIRST, int KSPLIT>
__global__ __launch_bounds__(128, 2) void moe_gemm_kernel(
    const float* __restrict__ A,     // x when FIRST (g_h otherwise)
    const float* __restrict__ B,     // w1 / w2  [E, KDIM, NDIM]
    const float* __restrict__ bias,  // [E, NDIM]
    float* __restrict__ out)
{
    const int zz = blockIdx.z;
    const int e  = zz / KSPLIT;
    const int ks = zz % KSPLIT;
    const int cnt = g_count[e];
    const int m0 = blockIdx.y * BM;
    if (m0 >= cnt) return;
    const int base = g_offset[e];
    const int n0 = blockIdx.x * BN;
    const int kbeg = ks * (KDIM / KSPLIT);

    extern __shared__ char dsm[];
    __shared__ int stok[BM];
    const uint32_t sb = smem_u32(dsm);

    const int tid  = threadIdx.x;
    const int wid  = tid >> 5;
    const int lane = tid & 31;
    const int gq = lane >> 2;   // 0..7
    const int tg = lane & 3;    // 0..3
    const int wm = wid >> 1;    // 0..1
    const int wn = wid & 1;     // 0..1

    if (FIRST) {
        if (tid < BM) {
            int r = m0 + tid;
            stok[tid] = (r < cnt) ? g_slot_token[base + r] : -1;
        }
    }
    __syncthreads();

    const float*  Apf = A;
    const __half* Aph = g_h;
    const float*  Bp  = B + (size_t)e * KDIM * NDIM;

    // staging maps (128 threads)
    const int a_r1 = tid >> 3;            // FIRST: row in 16-row group (0..15)
    const int a_c1 = (tid & 7) * 4;       // FIRST: k offset (floats)
    const int a_r2 = tid >> 2;            // !FIRST: row in 32-row group (0..31)
    const int a_c2 = (tid & 3) * 8;       // !FIRST: k offset (halves)
    const int b_r  = tid >> 4;            // 0..7
    const int b_c  = (tid & 15) * 4;      // 0..60

    // ldmatrix lane offsets (bytes within stage)
    const uint32_t a_lm = (uint32_t)(((wm * 64 + (lane & 15)) * SA + ((lane >> 4) << 3)) * 2);
    const uint32_t b_lm = (uint32_t)(((lane & 15) * SB + wn * 64 + ((lane >> 4) << 3)) * 2);

    float acc[4][8][4];
#pragma unroll
    for (int mi = 0; mi < 4; mi++)
#pragma unroll
        for (int ni = 0; ni < 8; ni++)
#pragma unroll
            for (int r = 0; r < 4; r++) acc[mi][ni][r] = 0.0f;

    // staging registers
    float4 la1[8];    // FIRST: 8 rounds x 16 rows
    uint4  la2[4];    // !FIRST: 4 rounds x 32 rows
    float4 lb[4][2];  // B: 4 k-rounds (8 rows) x 2 col-halves

    auto load_tile = [&](int k0) {
        if (FIRST) {
#pragma unroll
            for (int ro = 0; ro < 8; ro++) {
                int m = ro * 16 + a_r1;
                la1[ro] = make_float4(0.f, 0.f, 0.f, 0.f);
                int tk = stok[m];
                if (tk >= 0)
                    la1[ro] = *reinterpret_cast<const float4*>(
                        Apf + (size_t)tk * KDIM + k0 + a_c1);
            }
        } else {
#pragma unroll
            for (int ro = 0; ro < 4; ro++) {
                int m = ro * 32 + a_r2;
                la2[ro] = make_uint4(0u, 0u, 0u, 0u);
                if (m0 + m < cnt)
                    la2[ro] = *reinterpret_cast<const uint4*>(
                        Aph + (size_t)(base + m0 + m) * KDIM + k0 + a_c2);
            }
        }
#pragma unroll
        for (int ro = 0; ro < 4; ro++) {
            const float* brow = Bp + (size_t)(k0 + ro * 8 + b_r) * NDIM + n0 + b_c;
            lb[ro][0] = *reinterpret_cast<const float4*>(brow);
            lb[ro][1] = *reinterpret_cast<const float4*>(brow + 64);
        }
    };

    auto store_tile = [&](char* stage) {
        __half* As = reinterpret_cast<__half*>(stage);
        __half* Bs = reinterpret_cast<__half*>(stage + A_STAGE_B);
        if (FIRST) {
#pragma unroll
            for (int ro = 0; ro < 8; ro++) {
                int m = ro * 16 + a_r1;
                uint2 u;
                u.x = pack_h2(la1[ro].x, la1[ro].y);
                u.y = pack_h2(la1[ro].z, la1[ro].w);
                *reinterpret_cast<uint2*>(As + m * SA + a_c1) = u;
            }
        } else {
#pragma unroll
            for (int ro = 0; ro < 4; ro++) {
                int m = ro * 32 + a_r2;
                *reinterpret_cast<uint4*>(As + m * SA + a_c2) = la2[ro];
            }
        }
#pragma unroll
        for (int ro = 0; ro < 4; ro++) {
            int kl = ro * 8 + b_r;
#pragma unroll
            for (int h = 0; h < 2; h++) {
                uint2 u;
                u.x = pack_h2(lb[ro][h].x, lb[ro][h].y);
                u.y = pack_h2(lb[ro][h].z, lb[ro][h].w);
                *reinterpret_cast<uint2*>(Bs + kl * SB + h * 64 + b_c) = u;
            }
        }
    };

    // ---- prologue ----
    load_tile(kbeg);
    store_tile(dsm);
    __syncthreads();

    const int KT = (KDIM / KSPLIT) / BK;
    for (int kt = 0; kt < KT; kt++) {
        const int cur = kt & 1;
        const uint32_t a_base = sb + cur * STAGE_B + a_lm;
        const uint32_t b_base = sb + cur * STAGE_B + A_STAGE_B + b_lm;
        const bool more = (kt + 1 < KT);

        // issue next tile's global loads first (latency covered by kk=0 mmas)
        if (more) load_tile(kbeg + (kt + 1) * BK);

        uint32_t af[4][4], bf[8][2];

        // ---- kk = 0 chunk ----
#pragma unroll
        for (int mi = 0; mi < 4; mi++)
            ldsm_x4(a_base + (uint32_t)((mi * 16 * SA) * 2),
                    af[mi][0], af[mi][1], af[mi][2], af[mi][3]);
#pragma unroll
        for (int nj = 0; nj < 4; nj++)
            ldsm_x4_t(b_base + (uint32_t)((nj * 16) * 2),
                      bf[2 * nj][0], bf[2 * nj][1], bf[2 * nj + 1][0], bf[2 * nj + 1][1]);
#pragma unroll
        for (int mi = 0; mi < 4; mi++)
#pragma unroll
            for (int ni = 0; ni < 8; ni++)
                mma_f16(acc[mi][ni], af[mi], bf[ni]);

        // ---- kk = 16 chunk: ldmatrix, then STS of next stage, then mma ----
#pragma unroll
        for (int mi = 0; mi < 4; mi++)
            ldsm_x4(a_base + (uint32_t)((mi * 16 * SA + 16) * 2),
                    af[mi][0], af[mi][1], af[mi][2], af[mi][3]);
#pragma unroll
        for (int nj = 0; nj < 4; nj++)
            ldsm_x4_t(b_base + (uint32_t)((16 * SB + nj * 16) * 2),
                      bf[2 * nj][0], bf[2 * nj][1], bf[2 * nj + 1][0], bf[2 * nj + 1][1]);

        if (more) store_tile(dsm + (cur ^ 1) * STAGE_B);

#pragma unroll
        for (int mi = 0; mi < 4; mi++)
#pragma unroll
            for (int ni = 0; ni < 8; ni++)
                mma_f16(acc[mi][ni], af[mi], bf[ni]);

        __syncthreads();
    }

    // ---- epilogue: per-warp 64x64 smem transpose, coalesced writes ----
    float* scr = reinterpret_cast<float*>(dsm) + wid * 64 * EPI_STRIDE;
#pragma unroll
    for (int mi = 0; mi < 4; mi++)
#pragma unroll
        for (int ni = 0; ni < 8; ni++)
#pragma unroll
            for (int r = 0; r < 4; r++) {
                int rr = mi * 16 + gq + ((r >= 2) ? 8 : 0);
                int cc = ni * 8 + 2 * tg + (r & 1);
                scr[rr * EPI_STRIDE + cc] = acc[mi][ni][r];
            }
    __syncwarp();

    const int gcol = n0 + wn * 64 + 2 * lane;
    float2 bv = make_float2(0.f, 0.f);
    if (FIRST || ks == 0)
        bv = *reinterpret_cast<const float2*>(bias + (size_t)e * NDIM + gcol);

#pragma unroll 4
    for (int rr = 0; rr < 64; rr++) {
        int slot = m0 + wm * 64 + rr;
        if (slot < cnt) {
            float2 v = *reinterpret_cast<const float2*>(&scr[rr * EPI_STRIDE + 2 * lane]);
            v.x += bv.x; v.y += bv.y;
            if (FIRST) {
                __half2 hv = __floats2half2_rn(fmaxf(v.x, 0.0f), fmaxf(v.y, 0.0f));
                *reinterpret_cast<__half2*>(
                    g_h + (size_t)(base + slot) * NDIM + gcol) = hv;
            } else {
                float wg = g_slot_weight[base + slot];
                int   tk = g_slot_token[base + slot];
                atomicAdd(out + (size_t)tk * NDIM + gcol,     wg * v.x);
                atomicAdd(out + (size_t)tk * NDIM + gcol + 1, wg * v.y);
            }
        }
    }
}

// ---------------- launch ----------------
extern "C" void kernel_launch(void* const* d_in, const int* in_sizes, int n_in,
                              void* d_out, int out_size) {
    (void)in_sizes; (void)n_in;
    const float* x  = (const float*)d_in[0];
    const float* gw = (const float*)d_in[1];
    const float* gb = (const float*)d_in[2];
    const float* w1 = (const float*)d_in[3];
    const float* b1 = (const float*)d_in[4];
    const float* w2 = (const float*)d_in[5];
    const float* b2 = (const float*)d_in[6];
    float* out = (float*)d_out;

    static bool attr_set = false;
    if (!attr_set) {
        cudaFuncSetAttribute(moe_gemm_kernel<DDIM, HDIM, true, 1>,
                             cudaFuncAttributeMaxDynamicSharedMemorySize, SMEM_GEMM_BYTES);
        cudaFuncSetAttribute(moe_gemm_kernel<HDIM, ODIM, false, 2>,
                             cudaFuncAttributeMaxDynamicSharedMemorySize, SMEM_GEMM_BYTES);
        attr_set = true;
    }

    cudaMemsetAsync(out, 0, (size_t)out_size * sizeof(float), 0);
    init_counts_kernel<<<1, 32>>>();
    gate_kernel<<<NTOK / 8, 256>>>(x, gw, gb);
    offsets_kernel<<<1, 32>>>();
    scatter_kernel<<<NTOK / 256, 256>>>();

    dim3 g1(HDIM / BN, NTOK / BM, NEXP);       // (32, 64, 8)
    moe_gemm_kernel<DDIM, HDIM, true, 1><<<g1, 128, SMEM_GEMM_BYTES>>>(x, w1, b1, nullptr);

    dim3 g2(ODIM / BN, NTOK / BM, NEXP * 2);   // (8, 64, 16) split-K=2
    moe_gemm_kernel<HDIM, ODIM, false, 2><<<g2, 128, SMEM_GEMM_BYTES>>>(nullptr, w2, b2, out);
}